// round 3
// baseline (speedup 1.0000x reference)
#include <cuda_runtime.h>
#include <cuda_fp16.h>

#define NN   50000
#define NE   800000
#define KIN  256
#define MOUT 128
#define NH   4
#define NB   196        // ceil(NN/256)

// Scratch (allocation-free rule: __device__ globals)
__device__ __align__(16) __half g_Wx_h[NN * MOUT];  // 12.8 MB fp16 copy for agg
__device__ __align__(16) float g_ssrc[NN * NH];
__device__ __align__(16) float g_sdst[NN * NH];
__device__ int g_cnt[NN];
__device__ int g_scan[NN];
__device__ int g_bsum[256];
__device__ int g_off[NN + 1];
__device__ int g_cur[NN];
__device__ int g_esrc[NE];

// ---------------------------------------------------------------------------
// CSR build
// ---------------------------------------------------------------------------
__global__ void zero_cnt_kernel() {
    int i = blockIdx.x * blockDim.x + threadIdx.x;
    if (i < NN) g_cnt[i] = 0;
}

__global__ void hist_kernel(const int* __restrict__ ei) {
    int e = blockIdx.x * blockDim.x + threadIdx.x;
    if (e < NE) atomicAdd(&g_cnt[ei[NE + e]], 1);
}

__global__ void scan1_kernel() {
    __shared__ int sh[256];
    int t = threadIdx.x;
    int i = blockIdx.x * 256 + t;
    int v = (i < NN) ? g_cnt[i] : 0;
    sh[t] = v;
    __syncthreads();
    #pragma unroll
    for (int ofs = 1; ofs < 256; ofs <<= 1) {
        int add = (t >= ofs) ? sh[t - ofs] : 0;
        __syncthreads();
        sh[t] += add;
        __syncthreads();
    }
    if (i < NN) g_scan[i] = sh[t];
    if (t == 255) g_bsum[blockIdx.x] = sh[255];
}

__global__ void scan2_kernel() {
    __shared__ int sh[256];
    int t = threadIdx.x;
    int v = (t < NB) ? g_bsum[t] : 0;
    sh[t] = v;
    __syncthreads();
    #pragma unroll
    for (int ofs = 1; ofs < 256; ofs <<= 1) {
        int add = (t >= ofs) ? sh[t - ofs] : 0;
        __syncthreads();
        sh[t] += add;
        __syncthreads();
    }
    g_bsum[t] = sh[t] - v;
}

__global__ void scan3_kernel() {
    int i = blockIdx.x * blockDim.x + threadIdx.x;
    if (i < NN) {
        g_off[i] = g_scan[i] - g_cnt[i] + g_bsum[i >> 8];
        g_cur[i] = 0;
    }
    if (i == 0) g_off[NN] = NE;
}

__global__ void fill_kernel(const int* __restrict__ ei) {
    int e = blockIdx.x * blockDim.x + threadIdx.x;
    if (e >= NE) return;
    int s = ei[e];
    int d = ei[NE + e];
    int pos = g_off[d] + atomicAdd(&g_cur[d], 1);
    g_esrc[pos] = s;
}

// ---------------------------------------------------------------------------
// GEMM 128x128x16 tile, 8x8 micro-tile, packed fp32x2 FMA (FFMA2).
// Epilogue: fp16 Wx store + fused per-head attention scores.
// ---------------------------------------------------------------------------
#define BM 128
#define BK 16

__device__ __forceinline__ unsigned long long pack2(float lo, float hi) {
    unsigned long long r;
    asm("mov.b64 %0, {%1, %2};" : "=l"(r) : "f"(lo), "f"(hi));
    return r;
}
__device__ __forceinline__ void unpack2(unsigned long long v, float& lo, float& hi) {
    asm("mov.b64 {%0, %1}, %2;" : "=f"(lo), "=f"(hi) : "l"(v));
}
__device__ __forceinline__ void ffma2(unsigned long long& acc,
                                      unsigned long long a,
                                      unsigned long long b) {
    asm("fma.rn.f32x2 %0, %1, %2, %0;" : "+l"(acc) : "l"(a), "l"(b));
}

__global__ __launch_bounds__(256)
void gemm_score_kernel(const float* __restrict__ x,
                       const float* __restrict__ W,
                       const float* __restrict__ aw) {
    __shared__ float Xs[BK][BM];
    __shared__ float Ws[BK][MOUT];

    int tid = threadIdx.x;
    int tx2 = tid & 15;        // col block: cols tx2*8 .. +8 (single head tx2>>2)
    int ty2 = tid >> 4;        // row block: rows ty2*8 .. +8
    int row0 = blockIdx.x * BM;

    unsigned long long acc2[8][4];
    #pragma unroll
    for (int i = 0; i < 8; i++)
        #pragma unroll
        for (int j = 0; j < 4; j++) acc2[i][j] = 0ull;

    for (int k0 = 0; k0 < KIN; k0 += BK) {
        // Load X tile: 128x16 = 512 float4, 2 per thread
        #pragma unroll
        for (int j = 0; j < 2; j++) {
            int idx = tid * 2 + j;      // 0..511
            int m   = idx >> 2;         // 0..127
            int kv  = (idx & 3) * 4;
            int row = row0 + m;
            float4 v = make_float4(0.f, 0.f, 0.f, 0.f);
            if (row < NN) v = *(const float4*)&x[row * KIN + k0 + kv];
            Xs[kv + 0][m] = v.x; Xs[kv + 1][m] = v.y;
            Xs[kv + 2][m] = v.z; Xs[kv + 3][m] = v.w;
        }
        // Load W tile: 128x16 = 512 float4, 2 per thread
        #pragma unroll
        for (int j = 0; j < 2; j++) {
            int idx = tid * 2 + j;
            int o   = idx >> 2;
            int kv  = (idx & 3) * 4;
            float4 v = *(const float4*)&W[o * KIN + k0 + kv];
            Ws[kv + 0][o] = v.x; Ws[kv + 1][o] = v.y;
            Ws[kv + 2][o] = v.z; Ws[kv + 3][o] = v.w;
        }
        __syncthreads();

        #pragma unroll
        for (int k = 0; k < BK; k++) {
            float4 b0 = *(float4*)&Ws[k][tx2 * 8];
            float4 b1 = *(float4*)&Ws[k][tx2 * 8 + 4];
            unsigned long long bb[4];
            bb[0] = pack2(b0.x, b0.y); bb[1] = pack2(b0.z, b0.w);
            bb[2] = pack2(b1.x, b1.y); bb[3] = pack2(b1.z, b1.w);
            float4 a0 = *(float4*)&Xs[k][ty2 * 8];
            float4 a1 = *(float4*)&Xs[k][ty2 * 8 + 4];
            float av[8] = {a0.x, a0.y, a0.z, a0.w, a1.x, a1.y, a1.z, a1.w};
            #pragma unroll
            for (int i = 0; i < 8; i++) {
                unsigned long long aa = pack2(av[i], av[i]);
                ffma2(acc2[i][0], aa, bb[0]);
                ffma2(acc2[i][1], aa, bb[1]);
                ffma2(acc2[i][2], aa, bb[2]);
                ffma2(acc2[i][3], aa, bb[3]);
            }
        }
        __syncthreads();
    }

    // Epilogue: fp16 Wx store + fused scores.
    int col0 = tx2 * 8;
    int h = tx2 >> 2;
    float as[8], ad[8];
    #pragma unroll
    for (int j = 0; j < 8; j++) {
        as[j] = aw[col0 + j - (h * 32) + h * 32];  // = aw[(col0+j) % ... ] — a_s indexed by d within head
    }
    // a_s is indexed by d = col % 32; a_d likewise at offset 32
    #pragma unroll
    for (int j = 0; j < 8; j++) {
        int dloc = (col0 + j) & 31;
        as[j] = aw[dloc];
        ad[j] = aw[32 + dloc];
    }

    #pragma unroll
    for (int i = 0; i < 8; i++) {
        int row = row0 + ty2 * 8 + i;
        if (row >= NN) break;
        float f[8];
        #pragma unroll
        for (int j = 0; j < 4; j++) unpack2(acc2[i][j], f[j * 2], f[j * 2 + 1]);

        // fp16 store (16B per thread-row, coalesced across tx2)
        __half2 h0 = __float22half2_rn(make_float2(f[0], f[1]));
        __half2 h1 = __float22half2_rn(make_float2(f[2], f[3]));
        __half2 h2 = __float22half2_rn(make_float2(f[4], f[5]));
        __half2 h3 = __float22half2_rn(make_float2(f[6], f[7]));
        uint4 u;
        u.x = *(unsigned*)&h0; u.y = *(unsigned*)&h1;
        u.z = *(unsigned*)&h2; u.w = *(unsigned*)&h3;
        *(uint4*)&g_Wx_h[row * MOUT + col0] = u;

        // partial scores over this thread's 8 cols (one head)
        float ps = 0.f, pd = 0.f;
        #pragma unroll
        for (int j = 0; j < 8; j++) { ps += f[j] * as[j]; pd += f[j] * ad[j]; }
        // reduce across the 4 threads (tx2 group) sharing this head & row;
        // lane = (ty2&1)*16 + tx2, so xor 1,2 stays within the tx2 quad
        ps += __shfl_xor_sync(0xffffffffu, ps, 1);
        ps += __shfl_xor_sync(0xffffffffu, ps, 2);
        pd += __shfl_xor_sync(0xffffffffu, pd, 1);
        pd += __shfl_xor_sync(0xffffffffu, pd, 2);
        if ((tx2 & 3) == 0) {
            g_ssrc[row * NH + h] = ps;
            g_sdst[row * NH + h] = pd;
        }
    }
}

// ---------------------------------------------------------------------------
// Aggregation: one warp per destination node, fp16 gather, fused ELU.
// ---------------------------------------------------------------------------
__device__ __forceinline__ float lrelu_exp(float v) {
    float r = v > 0.f ? v : 0.2f * v;
    return __expf(r);
}

__global__ __launch_bounds__(256)
void agg_kernel(float* __restrict__ out) {
    int d = blockIdx.x * 8 + (threadIdx.x >> 5);
    if (d >= NN) return;
    int lane = threadIdx.x & 31;
    int beg = g_off[d];
    int end = g_off[d + 1];

    float4 sd4 = *(const float4*)&g_sdst[d * 4];

    // Pass 1: denom
    float4 dn = make_float4(0.f, 0.f, 0.f, 0.f);
    for (int j = beg + lane; j < end; j += 32) {
        int s = g_esrc[j];
        float4 a = *(const float4*)&g_ssrc[s * 4];
        dn.x += lrelu_exp(a.x + sd4.x);
        dn.y += lrelu_exp(a.y + sd4.y);
        dn.z += lrelu_exp(a.z + sd4.z);
        dn.w += lrelu_exp(a.w + sd4.w);
    }
    #pragma unroll
    for (int m = 16; m; m >>= 1) {
        dn.x += __shfl_xor_sync(0xffffffffu, dn.x, m);
        dn.y += __shfl_xor_sync(0xffffffffu, dn.y, m);
        dn.z += __shfl_xor_sync(0xffffffffu, dn.z, m);
        dn.w += __shfl_xor_sync(0xffffffffu, dn.w, m);
    }

    int h = lane >> 3;
    float dnh = (h == 0) ? dn.x : (h == 1) ? dn.y : (h == 2) ? dn.z : dn.w;
    float adh = (h == 0) ? sd4.x : (h == 1) ? sd4.y : (h == 2) ? sd4.z : sd4.w;
    float invd = __fdividef(1.f, dnh + 1e-8f);

    // Pass 2: fp16 weighted gather (8B per lane per edge)
    float4 acc = make_float4(0.f, 0.f, 0.f, 0.f);
    #pragma unroll 2
    for (int j = beg; j < end; j++) {
        int s = g_esrc[j];                               // warp-uniform
        float al = lrelu_exp(g_ssrc[s * 4 + h] + adh) * invd;
        float2 raw = *(const float2*)&g_Wx_h[s * MOUT + lane * 4];
        __half2 h01 = ((__half2*)&raw)[0];
        __half2 h23 = ((__half2*)&raw)[1];
        float2 f01 = __half22float2(h01);
        float2 f23 = __half22float2(h23);
        acc.x += al * f01.x; acc.y += al * f01.y;
        acc.z += al * f23.x; acc.w += al * f23.y;
    }

    acc.x = acc.x > 0.f ? acc.x : expm1f(acc.x);
    acc.y = acc.y > 0.f ? acc.y : expm1f(acc.y);
    acc.z = acc.z > 0.f ? acc.z : expm1f(acc.z);
    acc.w = acc.w > 0.f ? acc.w : expm1f(acc.w);
    *(float4*)&out[d * MOUT + lane * 4] = acc;
}

// ---------------------------------------------------------------------------
extern "C" void kernel_launch(void* const* d_in, const int* in_sizes, int n_in,
                              void* d_out, int out_size) {
    const float* x  = (const float*)d_in[0];
    const int*   ei = (const int*)d_in[1];
    const float* W  = (const float*)d_in[2];
    const float* aw = (const float*)d_in[3];
    float* out = (float*)d_out;

    zero_cnt_kernel<<<NB, 256>>>();
    gemm_score_kernel<<<(NN + BM - 1) / BM, 256>>>(x, W, aw);
    hist_kernel<<<(NE + 255) / 256, 256>>>(ei);
    scan1_kernel<<<NB, 256>>>();
    scan2_kernel<<<1, 256>>>();
    scan3_kernel<<<NB, 256>>>();
    fill_kernel<<<(NE + 255) / 256, 256>>>(ei);
    agg_kernel<<<(NN + 7) / 8, 256>>>(out);
}

// round 4
// speedup vs baseline: 1.4648x; 1.4648x over previous
#include <cuda_runtime.h>
#include <cuda_fp16.h>

#define NN   50000
#define NE   800000
#define KIN  256
#define MOUT 128
#define NH   4
#define NB   196        // ceil(NN/256)

// Scratch (allocation-free rule: __device__ globals)
__device__ __align__(16) __half g_Wx_h[NN * MOUT];  // 12.8 MB fp16 Wx for agg
__device__ __align__(16) float g_ssrc[NN * NH];
__device__ __align__(16) float g_sdst[NN * NH];
__device__ int g_cnt[NN];
__device__ int g_scan[NN];
__device__ int g_bsum[256];
__device__ int g_off[NN + 1];
__device__ int g_cur[NN];
__device__ int g_esrc[NE];

// ---------------------------------------------------------------------------
// CSR build
// ---------------------------------------------------------------------------
__global__ void zero_cnt_kernel() {
    int i = blockIdx.x * blockDim.x + threadIdx.x;
    if (i < NN) g_cnt[i] = 0;
}

__global__ void hist_kernel(const int* __restrict__ ei) {
    int e = blockIdx.x * blockDim.x + threadIdx.x;
    if (e < NE) atomicAdd(&g_cnt[ei[NE + e]], 1);
}

__global__ void scan1_kernel() {
    __shared__ int sh[256];
    int t = threadIdx.x;
    int i = blockIdx.x * 256 + t;
    int v = (i < NN) ? g_cnt[i] : 0;
    sh[t] = v;
    __syncthreads();
    #pragma unroll
    for (int ofs = 1; ofs < 256; ofs <<= 1) {
        int add = (t >= ofs) ? sh[t - ofs] : 0;
        __syncthreads();
        sh[t] += add;
        __syncthreads();
    }
    if (i < NN) g_scan[i] = sh[t];
    if (t == 255) g_bsum[blockIdx.x] = sh[255];
}

__global__ void scan2_kernel() {
    __shared__ int sh[256];
    int t = threadIdx.x;
    int v = (t < NB) ? g_bsum[t] : 0;
    sh[t] = v;
    __syncthreads();
    #pragma unroll
    for (int ofs = 1; ofs < 256; ofs <<= 1) {
        int add = (t >= ofs) ? sh[t - ofs] : 0;
        __syncthreads();
        sh[t] += add;
        __syncthreads();
    }
    g_bsum[t] = sh[t] - v;
}

__global__ void scan3_kernel() {
    int i = blockIdx.x * blockDim.x + threadIdx.x;
    if (i < NN) {
        g_off[i] = g_scan[i] - g_cnt[i] + g_bsum[i >> 8];
        g_cur[i] = 0;
    }
    if (i == 0) g_off[NN] = NE;
}

__global__ void fill_kernel(const int* __restrict__ ei) {
    int e = blockIdx.x * blockDim.x + threadIdx.x;
    if (e >= NE) return;
    int s = ei[e];
    int d = ei[NE + e];
    int pos = g_off[d] + atomicAdd(&g_cur[d], 1);
    g_esrc[pos] = s;
}

// ---------------------------------------------------------------------------
// tf32 tensor-core GEMM: Wx = x @ W^T, 128x128 block tile, 8 warps (4x2),
// warp = 32x64 = 2x8 m16n8k8 tiles. Fused fp16 Wx store + per-head scores.
// ---------------------------------------------------------------------------
#define BMT 128
#define BKT 32
#define XPAD 36   // row stride (uints) for smem tiles: conflict-free + 16B rows

__device__ __forceinline__ unsigned f2tf32(float f) {
    unsigned u;
    asm("cvt.rna.tf32.f32 %0, %1;" : "=r"(u) : "f"(f));
    return u;
}

__device__ __forceinline__ void mma_tf32(float* c, const unsigned* a,
                                         unsigned b0, unsigned b1) {
    asm volatile(
        "mma.sync.aligned.m16n8k8.row.col.f32.tf32.tf32.f32 "
        "{%0,%1,%2,%3}, {%4,%5,%6,%7}, {%8,%9}, {%0,%1,%2,%3};"
        : "+f"(c[0]), "+f"(c[1]), "+f"(c[2]), "+f"(c[3])
        : "r"(a[0]), "r"(a[1]), "r"(a[2]), "r"(a[3]), "r"(b0), "r"(b1));
}

__global__ __launch_bounds__(256, 2)
void gemm_tf32_kernel(const float* __restrict__ x,
                      const float* __restrict__ W,
                      const float* __restrict__ aw) {
    __shared__ unsigned Xs[BMT * XPAD];
    __shared__ unsigned Ws[MOUT * XPAD];

    int tid  = threadIdx.x;
    int lane = tid & 31;
    int warp = tid >> 5;
    int g = lane >> 2;          // group id (row within tile)
    int t = lane & 3;           // thread in group (col pair)
    int wm = warp & 3;          // warp row block (32 rows)
    int wn = warp >> 2;         // warp col block (64 cols = 2 heads)
    int row0 = blockIdx.x * BMT;

    float c[2][8][4];
    #pragma unroll
    for (int tm = 0; tm < 2; tm++)
        #pragma unroll
        for (int tn = 0; tn < 8; tn++)
            #pragma unroll
            for (int i = 0; i < 4; i++) c[tm][tn][i] = 0.f;

    for (int k0 = 0; k0 < KIN; k0 += BKT) {
        // Stage X tile (128x32) and W tile (128x32), tf32-converted.
        #pragma unroll
        for (int j = 0; j < 4; j++) {
            int idx = tid + 256 * j;      // 0..1023
            int m   = idx >> 3;           // 0..127
            int kv  = (idx & 7) * 4;      // 0..28
            int row = row0 + m;
            float4 v = make_float4(0.f, 0.f, 0.f, 0.f);
            if (row < NN) v = *(const float4*)&x[row * KIN + k0 + kv];
            uint4 u;
            u.x = f2tf32(v.x); u.y = f2tf32(v.y);
            u.z = f2tf32(v.z); u.w = f2tf32(v.w);
            *(uint4*)&Xs[m * XPAD + kv] = u;

            float4 w4 = *(const float4*)&W[m * KIN + k0 + kv];
            uint4 uw;
            uw.x = f2tf32(w4.x); uw.y = f2tf32(w4.y);
            uw.z = f2tf32(w4.z); uw.w = f2tf32(w4.w);
            *(uint4*)&Ws[m * XPAD + kv] = uw;
        }
        __syncthreads();

        #pragma unroll
        for (int kk = 0; kk < BKT; kk += 8) {
            unsigned a[2][4];
            #pragma unroll
            for (int tm = 0; tm < 2; tm++) {
                int r = wm * 32 + tm * 16 + g;
                a[tm][0] = Xs[r * XPAD + kk + t];
                a[tm][1] = Xs[(r + 8) * XPAD + kk + t];
                a[tm][2] = Xs[r * XPAD + kk + t + 4];
                a[tm][3] = Xs[(r + 8) * XPAD + kk + t + 4];
            }
            #pragma unroll
            for (int tn = 0; tn < 8; tn++) {
                int n = wn * 64 + tn * 8 + g;
                unsigned b0 = Ws[n * XPAD + kk + t];
                unsigned b1 = Ws[n * XPAD + kk + t + 4];
                mma_tf32(c[0][tn], a[0], b0, b1);
                mma_tf32(c[1][tn], a[1], b0, b1);
            }
        }
        __syncthreads();
    }

    // a_s/a_d values for this thread's local columns (col%32 = q*8 + 2t + j)
    float as_r[4][2], ad_r[4][2];
    #pragma unroll
    for (int q = 0; q < 4; q++)
        #pragma unroll
        for (int j = 0; j < 2; j++) {
            as_r[q][j] = aw[q * 8 + 2 * t + j];
            ad_r[q][j] = aw[32 + q * 8 + 2 * t + j];
        }

    #pragma unroll
    for (int tm = 0; tm < 2; tm++)
    #pragma unroll
    for (int half = 0; half < 2; half++) {
        int row = row0 + wm * 32 + tm * 16 + half * 8 + g;

        if (row < NN) {
            #pragma unroll
            for (int tn = 0; tn < 8; tn++) {
                __half2 hv = __floats2half2_rn(c[tm][tn][half * 2],
                                               c[tm][tn][half * 2 + 1]);
                *(__half2*)&g_Wx_h[row * MOUT + wn * 64 + tn * 8 + 2 * t] = hv;
            }
        }

        #pragma unroll
        for (int hl = 0; hl < 2; hl++) {
            float ps = 0.f, pd = 0.f;
            #pragma unroll
            for (int q = 0; q < 4; q++)
                #pragma unroll
                for (int j = 0; j < 2; j++) {
                    float v = c[tm][hl * 4 + q][half * 2 + j];
                    ps += v * as_r[q][j];
                    pd += v * ad_r[q][j];
                }
            ps += __shfl_xor_sync(0xffffffffu, ps, 1);
            ps += __shfl_xor_sync(0xffffffffu, ps, 2);
            pd += __shfl_xor_sync(0xffffffffu, pd, 1);
            pd += __shfl_xor_sync(0xffffffffu, pd, 2);
            if (t == 0 && row < NN) {
                g_ssrc[row * NH + wn * 2 + hl] = ps;
                g_sdst[row * NH + wn * 2 + hl] = pd;
            }
        }
    }
}

// ---------------------------------------------------------------------------
// Aggregation: one warp per destination node, fp16 gather, fused ELU.
// ---------------------------------------------------------------------------
__device__ __forceinline__ float lrelu_exp(float v) {
    float r = v > 0.f ? v : 0.2f * v;
    return __expf(r);
}

__global__ __launch_bounds__(256)
void agg_kernel(float* __restrict__ out) {
    int d = blockIdx.x * 8 + (threadIdx.x >> 5);
    if (d >= NN) return;
    int lane = threadIdx.x & 31;
    int beg = g_off[d];
    int end = g_off[d + 1];

    float4 sd4 = *(const float4*)&g_sdst[d * 4];

    // Pass 1: denom
    float4 dn = make_float4(0.f, 0.f, 0.f, 0.f);
    for (int j = beg + lane; j < end; j += 32) {
        int s = g_esrc[j];
        float4 a = *(const float4*)&g_ssrc[s * 4];
        dn.x += lrelu_exp(a.x + sd4.x);
        dn.y += lrelu_exp(a.y + sd4.y);
        dn.z += lrelu_exp(a.z + sd4.z);
        dn.w += lrelu_exp(a.w + sd4.w);
    }
    #pragma unroll
    for (int m = 16; m; m >>= 1) {
        dn.x += __shfl_xor_sync(0xffffffffu, dn.x, m);
        dn.y += __shfl_xor_sync(0xffffffffu, dn.y, m);
        dn.z += __shfl_xor_sync(0xffffffffu, dn.z, m);
        dn.w += __shfl_xor_sync(0xffffffffu, dn.w, m);
    }

    int h = lane >> 3;
    float dnh = (h == 0) ? dn.x : (h == 1) ? dn.y : (h == 2) ? dn.z : dn.w;
    float adh = (h == 0) ? sd4.x : (h == 1) ? sd4.y : (h == 2) ? sd4.z : sd4.w;
    float invd = __fdividef(1.f, dnh + 1e-8f);

    // Pass 2: fp16 weighted gather (8B per lane per edge)
    float4 acc = make_float4(0.f, 0.f, 0.f, 0.f);
    #pragma unroll 2
    for (int j = beg; j < end; j++) {
        int s = g_esrc[j];                               // warp-uniform
        float al = lrelu_exp(g_ssrc[s * 4 + h] + adh) * invd;
        float2 raw = *(const float2*)&g_Wx_h[s * MOUT + lane * 4];
        __half2 h01 = ((__half2*)&raw)[0];
        __half2 h23 = ((__half2*)&raw)[1];
        float2 f01 = __half22float2(h01);
        float2 f23 = __half22float2(h23);
        acc.x += al * f01.x; acc.y += al * f01.y;
        acc.z += al * f23.x; acc.w += al * f23.y;
    }

    acc.x = acc.x > 0.f ? acc.x : expm1f(acc.x);
    acc.y = acc.y > 0.f ? acc.y : expm1f(acc.y);
    acc.z = acc.z > 0.f ? acc.z : expm1f(acc.z);
    acc.w = acc.w > 0.f ? acc.w : expm1f(acc.w);
    *(float4*)&out[d * MOUT + lane * 4] = acc;
}

// ---------------------------------------------------------------------------
extern "C" void kernel_launch(void* const* d_in, const int* in_sizes, int n_in,
                              void* d_out, int out_size) {
    const float* x  = (const float*)d_in[0];
    const int*   ei = (const int*)d_in[1];
    const float* W  = (const float*)d_in[2];
    const float* aw = (const float*)d_in[3];
    float* out = (float*)d_out;

    zero_cnt_kernel<<<NB, 256>>>();
    gemm_tf32_kernel<<<(NN + BMT - 1) / BMT, 256>>>(x, W, aw);
    hist_kernel<<<(NE + 255) / 256, 256>>>(ei);
    scan1_kernel<<<NB, 256>>>();
    scan2_kernel<<<1, 256>>>();
    scan3_kernel<<<NB, 256>>>();
    fill_kernel<<<(NE + 255) / 256, 256>>>(ei);
    agg_kernel<<<(NN + 7) / 8, 256>>>(out);
}